// round 6
// baseline (speedup 1.0000x reference)
#include <cuda_runtime.h>
#include <cuda_bf16.h>
#include <cstdint>

#define N_NODES 50000
#define N_EDGES 800000
#define IN_DIM  256
#define HID     128
#define LEAKY   0.01f

// ---------------- scratch (static device allocations only) ----------------
__device__ __align__(16) float g_z[N_NODES * HID];     // fc output per layer
__device__ __align__(16) float g_h1[N_NODES * HID];    // layer-1 result (ELU applied)
__device__ float g_s[N_NODES];                          // z . a[:D]
__device__ float g_t[N_NODES];                          // z . a[D:]
__device__ int   g_cnt[N_NODES];                        // in-degree histogram
__device__ int   g_cur[N_NODES];                        // fill cursors
__device__ int   g_off[N_NODES + 1];                    // CSR offsets
__device__ __align__(16) int g_csr[N_EDGES];            // src id per CSR slot

__device__ __forceinline__ float elu1(float x) {
    return x > 0.f ? x : (__expf(x) - 1.f);
}

// ================= CSR build (once per call, reused by both layers) ========
__global__ void k_zero() {
    int i = blockIdx.x * blockDim.x + threadIdx.x;
    if (i < N_NODES) { g_cnt[i] = 0; g_cur[i] = 0; }
}

// 4 edges/thread: 4 independent atomic chains (MLP=4)
__global__ void k_hist(const int* __restrict__ dst) {
    int i = (blockIdx.x * blockDim.x + threadIdx.x) * 4;
    if (i + 3 < N_EDGES) {
        int4 d = *(const int4*)(dst + i);
        atomicAdd(&g_cnt[d.x], 1);
        atomicAdd(&g_cnt[d.y], 1);
        atomicAdd(&g_cnt[d.z], 1);
        atomicAdd(&g_cnt[d.w], 1);
    } else {
        for (; i < N_EDGES; i++) atomicAdd(&g_cnt[dst[i]], 1);
    }
}

__global__ void __launch_bounds__(1024) k_scan() {
    const int ITEMS = (N_NODES + 1023) / 1024;   // 49
    int t = threadIdx.x, lane = t & 31, wid = t >> 5;
    int base = t * ITEMS;

    int sum = 0;
#pragma unroll
    for (int i = 0; i < ITEMS; i++) {
        int idx = base + i;
        if (idx < N_NODES) sum += g_cnt[idx];
    }
    int v = sum;
#pragma unroll
    for (int off = 1; off < 32; off <<= 1) {
        int n = __shfl_up_sync(0xffffffffu, v, off);
        if (lane >= off) v += n;
    }
    __shared__ int wsum[32];
    if (lane == 31) wsum[wid] = v;
    __syncthreads();
    if (wid == 0) {
        int w = wsum[lane];
#pragma unroll
        for (int off = 1; off < 32; off <<= 1) {
            int n = __shfl_up_sync(0xffffffffu, w, off);
            if (lane >= off) w += n;
        }
        wsum[lane] = w;
    }
    __syncthreads();
    int excl = v - sum + (wid > 0 ? wsum[wid - 1] : 0);

    int run = excl;
#pragma unroll
    for (int i = 0; i < ITEMS; i++) {
        int idx = base + i;
        if (idx < N_NODES) { g_off[idx] = run; run += g_cnt[idx]; }
    }
    if (t == 0) g_off[N_NODES] = N_EDGES;
}

// 4 edges/thread: 4 independent LDG->ATOM->STG chains
__global__ void k_fill(const int* __restrict__ src, const int* __restrict__ dst) {
    int i = (blockIdx.x * blockDim.x + threadIdx.x) * 4;
    if (i + 3 < N_EDGES) {
        int4 d = *(const int4*)(dst + i);
        int4 s = *(const int4*)(src + i);
        int o0 = g_off[d.x], o1 = g_off[d.y], o2 = g_off[d.z], o3 = g_off[d.w];
        g_csr[o0 + atomicAdd(&g_cur[d.x], 1)] = s.x;
        g_csr[o1 + atomicAdd(&g_cur[d.y], 1)] = s.y;
        g_csr[o2 + atomicAdd(&g_cur[d.z], 1)] = s.z;
        g_csr[o3 + atomicAdd(&g_cur[d.w], 1)] = s.w;
    } else {
        for (; i < N_EDGES; i++) {
            int d = dst[i];
            g_csr[g_off[d] + atomicAdd(&g_cur[d], 1)] = src[i];
        }
    }
}

// ============ tensor-core GEMM: z = X @ W^T + b  (bf16 hi/lo split) ========
__device__ __forceinline__ void mma16816(float d[4], const uint32_t a[4],
                                         const uint32_t b[2]) {
    asm volatile(
        "mma.sync.aligned.m16n8k16.row.col.f32.bf16.bf16.f32 "
        "{%0,%1,%2,%3}, {%4,%5,%6,%7}, {%8,%9}, {%0,%1,%2,%3};"
        : "+f"(d[0]), "+f"(d[1]), "+f"(d[2]), "+f"(d[3])
        : "r"(a[0]), "r"(a[1]), "r"(a[2]), "r"(a[3]), "r"(b[0]), "r"(b[1]));
}

#define SSTR 40   // smem K-stride in bf16 elems (80B) -> conflict-free frags

template <int K>
__global__ void __launch_bounds__(256) k_gemm_tc(
    const float* __restrict__ X,          // nullptr -> g_h1
    const float* __restrict__ W,
    const float* __restrict__ bias,
    const float* __restrict__ a)          // length 2*HID
{
    __shared__ __nv_bfloat16 sAh[128][SSTR], sAl[128][SSTR];
    __shared__ __nv_bfloat16 sBh[128][SSTR], sBl[128][SSTR];
    __shared__ float s_part[2][128], t_part[2][128];

    const float* __restrict__ Xp = X ? X : g_h1;

    const int tid   = threadIdx.x;
    const int wid   = tid >> 5;
    const int lane  = tid & 31;
    const int g     = lane >> 2;
    const int tig   = lane & 3;
    const int warpM = wid & 3;
    const int warpN = wid >> 2;
    const int row0  = blockIdx.x * 128;

    float acc[2][8][4];
#pragma unroll
    for (int mt = 0; mt < 2; mt++)
#pragma unroll
        for (int nt = 0; nt < 8; nt++)
#pragma unroll
            for (int r = 0; r < 4; r++) acc[mt][nt][r] = 0.f;

    for (int k0 = 0; k0 < K; k0 += 32) {
#pragma unroll
        for (int v = 0; v < 4; v++) {
            int q  = tid + v * 256;
            int r  = q >> 3;
            int kq = (q & 7) << 2;
            int gr = row0 + r;
            float4 xv = make_float4(0.f, 0.f, 0.f, 0.f);
            if (gr < N_NODES)
                xv = *(const float4*)(Xp + (size_t)gr * K + k0 + kq);
            float4 wv = *(const float4*)(W + (size_t)r * K + k0 + kq);
            const float* xs = &xv.x;
            const float* ws = &wv.x;
#pragma unroll
            for (int i = 0; i < 4; i++) {
                float x = xs[i];
                __nv_bfloat16 hx = __float2bfloat16(x);
                sAh[r][kq + i] = hx;
                sAl[r][kq + i] = __float2bfloat16(x - __bfloat162float(hx));
                float w = ws[i];
                __nv_bfloat16 hw = __float2bfloat16(w);
                sBh[r][kq + i] = hw;
                sBl[r][kq + i] = __float2bfloat16(w - __bfloat162float(hw));
            }
        }
        __syncthreads();

#pragma unroll
        for (int ks = 0; ks < 32; ks += 16) {
            uint32_t ah[2][4], al[2][4];
#pragma unroll
            for (int mt = 0; mt < 2; mt++) {
                int r = warpM * 32 + mt * 16 + g;
                int kk = ks + tig * 2;
                ah[mt][0] = *(const uint32_t*)&sAh[r][kk];
                ah[mt][1] = *(const uint32_t*)&sAh[r + 8][kk];
                ah[mt][2] = *(const uint32_t*)&sAh[r][kk + 8];
                ah[mt][3] = *(const uint32_t*)&sAh[r + 8][kk + 8];
                al[mt][0] = *(const uint32_t*)&sAl[r][kk];
                al[mt][1] = *(const uint32_t*)&sAl[r + 8][kk];
                al[mt][2] = *(const uint32_t*)&sAl[r][kk + 8];
                al[mt][3] = *(const uint32_t*)&sAl[r + 8][kk + 8];
            }
            uint32_t bh[8][2], bl[8][2];
#pragma unroll
            for (int nt = 0; nt < 8; nt++) {
                int c = warpN * 64 + nt * 8 + g;
                int kk = ks + tig * 2;
                bh[nt][0] = *(const uint32_t*)&sBh[c][kk];
                bh[nt][1] = *(const uint32_t*)&sBh[c][kk + 8];
                bl[nt][0] = *(const uint32_t*)&sBl[c][kk];
                bl[nt][1] = *(const uint32_t*)&sBl[c][kk + 8];
            }
#pragma unroll
            for (int mt = 0; mt < 2; mt++)
#pragma unroll
                for (int nt = 0; nt < 8; nt++) {
                    mma16816(acc[mt][nt], ah[mt], bh[nt]);
                    mma16816(acc[mt][nt], ah[mt], bl[nt]);
                    mma16816(acc[mt][nt], al[mt], bh[nt]);
                }
        }
        __syncthreads();
    }

    float sp[2][2] = {{0.f, 0.f}, {0.f, 0.f}};
    float tp[2][2] = {{0.f, 0.f}, {0.f, 0.f}};
#pragma unroll
    for (int mt = 0; mt < 2; mt++) {
        int rA = row0 + warpM * 32 + mt * 16 + g;
        int rB = rA + 8;
#pragma unroll
        for (int nt = 0; nt < 8; nt++) {
            int c0 = warpN * 64 + nt * 8 + tig * 2;
            float bb0 = bias[c0], bb1 = bias[c0 + 1];
            float a0s = a[c0], a1s = a[c0 + 1];
            float a0d = a[HID + c0], a1d = a[HID + c0 + 1];
            float v0 = acc[mt][nt][0] + bb0;
            float v1 = acc[mt][nt][1] + bb1;
            float v2 = acc[mt][nt][2] + bb0;
            float v3 = acc[mt][nt][3] + bb1;
            if (rA < N_NODES)
                *(float2*)(&g_z[(size_t)rA * HID + c0]) = make_float2(v0, v1);
            if (rB < N_NODES)
                *(float2*)(&g_z[(size_t)rB * HID + c0]) = make_float2(v2, v3);
            sp[mt][0] = fmaf(v0, a0s, fmaf(v1, a1s, sp[mt][0]));
            tp[mt][0] = fmaf(v0, a0d, fmaf(v1, a1d, tp[mt][0]));
            sp[mt][1] = fmaf(v2, a0s, fmaf(v3, a1s, sp[mt][1]));
            tp[mt][1] = fmaf(v2, a0d, fmaf(v3, a1d, tp[mt][1]));
        }
    }
#pragma unroll
    for (int mt = 0; mt < 2; mt++)
#pragma unroll
        for (int hh = 0; hh < 2; hh++) {
            float s = sp[mt][hh], t = tp[mt][hh];
            s += __shfl_xor_sync(0xffffffffu, s, 1);
            s += __shfl_xor_sync(0xffffffffu, s, 2);
            t += __shfl_xor_sync(0xffffffffu, t, 1);
            t += __shfl_xor_sync(0xffffffffu, t, 2);
            if (tig == 0) {
                int lr = warpM * 32 + mt * 16 + hh * 8 + g;
                s_part[warpN][lr] = s;
                t_part[warpN][lr] = t;
            }
        }
    __syncthreads();
    if (tid < 128) {
        int gr = row0 + tid;
        if (gr < N_NODES) {
            g_s[gr] = s_part[0][tid] + s_part[1][tid];
            g_t[gr] = t_part[0][tid] + t_part[1][tid];
        }
    }
}

// ======== aggregate: per-dst gather, softmax weight, normalize, ELU ========
// One warp per dst node. Lane-parallel logit/exp phase (32 at once), shuffle
// distribution, independent z gathers unrolled x4. No atomics.
__global__ void __launch_bounds__(256) k_agg(const float* __restrict__ abp,
                                             float* __restrict__ out) {
    int node = (blockIdx.x * blockDim.x + threadIdx.x) >> 5;
    if (node >= N_NODES) return;
    int lane = threadIdx.x & 31;
    float* __restrict__ op = out ? out : g_h1;

    int   off0 = g_off[node];
    int   off1 = g_off[node + 1];
    float td   = g_t[node] + abp[0];

    float4 acc = make_float4(0.f, 0.f, 0.f, 0.f);
    float  den = 0.f;
    const size_t zlane = (size_t)lane * 4;

    for (int base = off0; base < off1; base += 32) {
        int cnt = off1 - base;
        if (cnt > 32) cnt = 32;

        // lane-parallel: each lane owns one edge of this chunk
        int   sidx = 0;
        float ex   = 0.f;
        if (lane < cnt) {
            sidx = g_csr[base + lane];
            float e = g_s[sidx] + td;
            e  = e > 0.f ? e : LEAKY * e;
            ex = __expf(e);
        }
        den += ex;

        // distribute via shfl; z gathers are independent -> deep MLP
        int e = 0;
        for (; e + 4 <= cnt; e += 4) {
            int   s0 = __shfl_sync(0xffffffffu, sidx, e);
            int   s1 = __shfl_sync(0xffffffffu, sidx, e + 1);
            int   s2 = __shfl_sync(0xffffffffu, sidx, e + 2);
            int   s3 = __shfl_sync(0xffffffffu, sidx, e + 3);
            float x0 = __shfl_sync(0xffffffffu, ex, e);
            float x1 = __shfl_sync(0xffffffffu, ex, e + 1);
            float x2 = __shfl_sync(0xffffffffu, ex, e + 2);
            float x3 = __shfl_sync(0xffffffffu, ex, e + 3);
            float4 z0 = *(const float4*)(&g_z[(size_t)s0 * HID + zlane]);
            float4 z1 = *(const float4*)(&g_z[(size_t)s1 * HID + zlane]);
            float4 z2 = *(const float4*)(&g_z[(size_t)s2 * HID + zlane]);
            float4 z3 = *(const float4*)(&g_z[(size_t)s3 * HID + zlane]);
            acc.x = fmaf(x0, z0.x, acc.x); acc.y = fmaf(x0, z0.y, acc.y);
            acc.z = fmaf(x0, z0.z, acc.z); acc.w = fmaf(x0, z0.w, acc.w);
            acc.x = fmaf(x1, z1.x, acc.x); acc.y = fmaf(x1, z1.y, acc.y);
            acc.z = fmaf(x1, z1.z, acc.z); acc.w = fmaf(x1, z1.w, acc.w);
            acc.x = fmaf(x2, z2.x, acc.x); acc.y = fmaf(x2, z2.y, acc.y);
            acc.z = fmaf(x2, z2.z, acc.z); acc.w = fmaf(x2, z2.w, acc.w);
            acc.x = fmaf(x3, z3.x, acc.x); acc.y = fmaf(x3, z3.y, acc.y);
            acc.z = fmaf(x3, z3.z, acc.z); acc.w = fmaf(x3, z3.w, acc.w);
        }
        for (; e < cnt; e++) {
            int   s0 = __shfl_sync(0xffffffffu, sidx, e);
            float x0 = __shfl_sync(0xffffffffu, ex, e);
            float4 z0 = *(const float4*)(&g_z[(size_t)s0 * HID + zlane]);
            acc.x = fmaf(x0, z0.x, acc.x); acc.y = fmaf(x0, z0.y, acc.y);
            acc.z = fmaf(x0, z0.z, acc.z); acc.w = fmaf(x0, z0.w, acc.w);
        }
    }

    // reduce den across lanes (each lane holds partial from its owned edges)
#pragma unroll
    for (int off = 16; off > 0; off >>= 1)
        den += __shfl_xor_sync(0xffffffffu, den, off);

    float inv = den > 0.f ? 1.f / den : 0.f;
    float4 r;
    r.x = elu1(acc.x * inv);
    r.y = elu1(acc.y * inv);
    r.z = elu1(acc.z * inv);
    r.w = elu1(acc.w * inv);
    *(float4*)(&op[(size_t)node * HID + zlane]) = r;
}

// ---------------- launch ----------------
extern "C" void kernel_launch(void* const* d_in, const int* in_sizes, int n_in,
                              void* d_out, int out_size) {
    const float* h   = (const float*)d_in[0];
    const int*   src = (const int*)d_in[1];
    const int*   dst = (const int*)d_in[2];
    const float* W1  = (const float*)d_in[3];
    const float* b1  = (const float*)d_in[4];
    const float* a1  = (const float*)d_in[5];
    const float* ab1 = (const float*)d_in[6];
    const float* W2  = (const float*)d_in[7];
    const float* b2  = (const float*)d_in[8];
    const float* a2  = (const float*)d_in[9];
    const float* ab2 = (const float*)d_in[10];
    float* out = (float*)d_out;

    const int zeroB  = (N_NODES + 255) / 256;
    const int edge4B = (N_EDGES / 4 + 255) / 256;
    const int gemmB  = (N_NODES + 127) / 128;
    const int aggB   = (N_NODES * 32 + 255) / 256;

    // ---- CSR build (shared by both layers) ----
    k_zero<<<zeroB, 256>>>();
    k_hist<<<edge4B, 256>>>(dst);
    k_scan<<<1, 1024>>>();
    k_fill<<<edge4B, 256>>>(src, dst);

    // ---- layer 1 ----
    k_gemm_tc<IN_DIM><<<gemmB, 256>>>(h, W1, b1, a1);
    k_agg<<<aggB, 256>>>(ab1, nullptr);        // -> g_h1 (ELU applied)

    // ---- layer 2 ----
    k_gemm_tc<HID><<<gemmB, 256>>>(nullptr, W2, b2, a2);   // X = g_h1
    k_agg<<<aggB, 256>>>(ab2, out);
}

// round 7
// speedup vs baseline: 1.0298x; 1.0298x over previous
#include <cuda_runtime.h>
#include <cuda_bf16.h>
#include <cstdint>

#define N_NODES 50000
#define N_EDGES 800000
#define IN_DIM  256
#define HID     128
#define LEAKY   0.01f

// ---------------- scratch (static device allocations only) ----------------
__device__ __align__(16) float g_z[N_NODES * HID];     // fc output per layer
__device__ __align__(16) float g_h1[N_NODES * HID];    // layer-1 result (ELU applied)
__device__ float g_s[N_NODES];                          // z . a[:D]
__device__ float g_t[N_NODES];                          // z . a[D:]
__device__ int   g_cnt[N_NODES];                        // in-degree histogram
__device__ int   g_rank[N_EDGES];                       // edge rank within dst seg
__device__ int   g_off[N_NODES + 1];                    // CSR offsets
__device__ int   g_csr[N_EDGES];                        // src id per CSR slot

__device__ __forceinline__ float elu1(float x) {
    return x > 0.f ? x : (__expf(x) - 1.f);
}

// ================= CSR build (once per call, reused by both layers) ========
__global__ void k_zero() {
    int i = blockIdx.x * blockDim.x + threadIdx.x;
    if (i < N_NODES) g_cnt[i] = 0;
}

// histogram; atomic return value = this edge's rank within its dst segment
__global__ void k_hist(const int* __restrict__ dst) {
    int i = blockIdx.x * blockDim.x + threadIdx.x;
    if (i < N_EDGES) g_rank[i] = atomicAdd(&g_cnt[dst[i]], 1);
}

__global__ void __launch_bounds__(1024) k_scan() {
    const int ITEMS = (N_NODES + 1023) / 1024;   // 49
    int t = threadIdx.x, lane = t & 31, wid = t >> 5;
    int base = t * ITEMS;

    int sum = 0;
#pragma unroll
    for (int i = 0; i < ITEMS; i++) {
        int idx = base + i;
        if (idx < N_NODES) sum += g_cnt[idx];
    }
    int v = sum;
#pragma unroll
    for (int off = 1; off < 32; off <<= 1) {
        int n = __shfl_up_sync(0xffffffffu, v, off);
        if (lane >= off) v += n;
    }
    __shared__ int wsum[32];
    if (lane == 31) wsum[wid] = v;
    __syncthreads();
    if (wid == 0) {
        int w = wsum[lane];
#pragma unroll
        for (int off = 1; off < 32; off <<= 1) {
            int n = __shfl_up_sync(0xffffffffu, w, off);
            if (lane >= off) w += n;
        }
        wsum[lane] = w;
    }
    __syncthreads();
    int excl = v - sum + (wid > 0 ? wsum[wid - 1] : 0);

    int run = excl;
#pragma unroll
    for (int i = 0; i < ITEMS; i++) {
        int idx = base + i;
        if (idx < N_NODES) { g_off[idx] = run; run += g_cnt[idx]; }
    }
    if (t == 0) g_off[N_NODES] = N_EDGES;
}

// atomic-free fill: slot = off[dst] + precomputed rank
__global__ void k_fill(const int* __restrict__ src, const int* __restrict__ dst) {
    int i = blockIdx.x * blockDim.x + threadIdx.x;
    if (i >= N_EDGES) return;
    g_csr[g_off[dst[i]] + g_rank[i]] = src[i];
}

// ============ tensor-core GEMM: z = X @ W^T + b  (bf16 hi/lo split) ========
__device__ __forceinline__ void mma16816(float d[4], const uint32_t a[4],
                                         const uint32_t b[2]) {
    asm volatile(
        "mma.sync.aligned.m16n8k16.row.col.f32.bf16.bf16.f32 "
        "{%0,%1,%2,%3}, {%4,%5,%6,%7}, {%8,%9}, {%0,%1,%2,%3};"
        : "+f"(d[0]), "+f"(d[1]), "+f"(d[2]), "+f"(d[3])
        : "r"(a[0]), "r"(a[1]), "r"(a[2]), "r"(a[3]), "r"(b[0]), "r"(b[1]));
}

#define SSTR 40   // smem K-stride in bf16 elems (80B) -> conflict-free frags

template <int K>
__global__ void __launch_bounds__(256) k_gemm_tc(
    const float* __restrict__ X,          // nullptr -> g_h1
    const float* __restrict__ W,
    const float* __restrict__ bias,
    const float* __restrict__ a)          // length 2*HID
{
    __shared__ __nv_bfloat16 sAh[128][SSTR], sAl[128][SSTR];
    __shared__ __nv_bfloat16 sBh[128][SSTR], sBl[128][SSTR];
    __shared__ float s_part[2][128], t_part[2][128];

    const float* __restrict__ Xp = X ? X : g_h1;

    const int tid   = threadIdx.x;
    const int wid   = tid >> 5;
    const int lane  = tid & 31;
    const int g     = lane >> 2;
    const int tig   = lane & 3;
    const int warpM = wid & 3;
    const int warpN = wid >> 2;
    const int row0  = blockIdx.x * 128;

    float acc[2][8][4];
#pragma unroll
    for (int mt = 0; mt < 2; mt++)
#pragma unroll
        for (int nt = 0; nt < 8; nt++)
#pragma unroll
            for (int r = 0; r < 4; r++) acc[mt][nt][r] = 0.f;

    for (int k0 = 0; k0 < K; k0 += 32) {
#pragma unroll
        for (int v = 0; v < 4; v++) {
            int q  = tid + v * 256;
            int r  = q >> 3;
            int kq = (q & 7) << 2;
            int gr = row0 + r;
            float4 xv = make_float4(0.f, 0.f, 0.f, 0.f);
            if (gr < N_NODES)
                xv = *(const float4*)(Xp + (size_t)gr * K + k0 + kq);
            float4 wv = *(const float4*)(W + (size_t)r * K + k0 + kq);
            const float* xs = &xv.x;
            const float* ws = &wv.x;
#pragma unroll
            for (int i = 0; i < 4; i++) {
                float x = xs[i];
                __nv_bfloat16 hx = __float2bfloat16(x);
                sAh[r][kq + i] = hx;
                sAl[r][kq + i] = __float2bfloat16(x - __bfloat162float(hx));
                float w = ws[i];
                __nv_bfloat16 hw = __float2bfloat16(w);
                sBh[r][kq + i] = hw;
                sBl[r][kq + i] = __float2bfloat16(w - __bfloat162float(hw));
            }
        }
        __syncthreads();

#pragma unroll
        for (int ks = 0; ks < 32; ks += 16) {
            uint32_t ah[2][4], al[2][4];
#pragma unroll
            for (int mt = 0; mt < 2; mt++) {
                int r = warpM * 32 + mt * 16 + g;
                int kk = ks + tig * 2;
                ah[mt][0] = *(const uint32_t*)&sAh[r][kk];
                ah[mt][1] = *(const uint32_t*)&sAh[r + 8][kk];
                ah[mt][2] = *(const uint32_t*)&sAh[r][kk + 8];
                ah[mt][3] = *(const uint32_t*)&sAh[r + 8][kk + 8];
                al[mt][0] = *(const uint32_t*)&sAl[r][kk];
                al[mt][1] = *(const uint32_t*)&sAl[r + 8][kk];
                al[mt][2] = *(const uint32_t*)&sAl[r][kk + 8];
                al[mt][3] = *(const uint32_t*)&sAl[r + 8][kk + 8];
            }
            uint32_t bh[8][2], bl[8][2];
#pragma unroll
            for (int nt = 0; nt < 8; nt++) {
                int c = warpN * 64 + nt * 8 + g;
                int kk = ks + tig * 2;
                bh[nt][0] = *(const uint32_t*)&sBh[c][kk];
                bh[nt][1] = *(const uint32_t*)&sBh[c][kk + 8];
                bl[nt][0] = *(const uint32_t*)&sBl[c][kk];
                bl[nt][1] = *(const uint32_t*)&sBl[c][kk + 8];
            }
#pragma unroll
            for (int mt = 0; mt < 2; mt++)
#pragma unroll
                for (int nt = 0; nt < 8; nt++) {
                    mma16816(acc[mt][nt], ah[mt], bh[nt]);
                    mma16816(acc[mt][nt], ah[mt], bl[nt]);
                    mma16816(acc[mt][nt], al[mt], bh[nt]);
                }
        }
        __syncthreads();
    }

    float sp[2][2] = {{0.f, 0.f}, {0.f, 0.f}};
    float tp[2][2] = {{0.f, 0.f}, {0.f, 0.f}};
#pragma unroll
    for (int mt = 0; mt < 2; mt++) {
        int rA = row0 + warpM * 32 + mt * 16 + g;
        int rB = rA + 8;
#pragma unroll
        for (int nt = 0; nt < 8; nt++) {
            int c0 = warpN * 64 + nt * 8 + tig * 2;
            float bb0 = bias[c0], bb1 = bias[c0 + 1];
            float a0s = a[c0], a1s = a[c0 + 1];
            float a0d = a[HID + c0], a1d = a[HID + c0 + 1];
            float v0 = acc[mt][nt][0] + bb0;
            float v1 = acc[mt][nt][1] + bb1;
            float v2 = acc[mt][nt][2] + bb0;
            float v3 = acc[mt][nt][3] + bb1;
            if (rA < N_NODES)
                *(float2*)(&g_z[(size_t)rA * HID + c0]) = make_float2(v0, v1);
            if (rB < N_NODES)
                *(float2*)(&g_z[(size_t)rB * HID + c0]) = make_float2(v2, v3);
            sp[mt][0] = fmaf(v0, a0s, fmaf(v1, a1s, sp[mt][0]));
            tp[mt][0] = fmaf(v0, a0d, fmaf(v1, a1d, tp[mt][0]));
            sp[mt][1] = fmaf(v2, a0s, fmaf(v3, a1s, sp[mt][1]));
            tp[mt][1] = fmaf(v2, a0d, fmaf(v3, a1d, tp[mt][1]));
        }
    }
#pragma unroll
    for (int mt = 0; mt < 2; mt++)
#pragma unroll
        for (int hh = 0; hh < 2; hh++) {
            float s = sp[mt][hh], t = tp[mt][hh];
            s += __shfl_xor_sync(0xffffffffu, s, 1);
            s += __shfl_xor_sync(0xffffffffu, s, 2);
            t += __shfl_xor_sync(0xffffffffu, t, 1);
            t += __shfl_xor_sync(0xffffffffu, t, 2);
            if (tig == 0) {
                int lr = warpM * 32 + mt * 16 + hh * 8 + g;
                s_part[warpN][lr] = s;
                t_part[warpN][lr] = t;
            }
        }
    __syncthreads();
    if (tid < 128) {
        int gr = row0 + tid;
        if (gr < N_NODES) {
            g_s[gr] = s_part[0][tid] + s_part[1][tid];
            g_t[gr] = t_part[0][tid] + t_part[1][tid];
        }
    }
}

// ======== aggregate: per-dst gather, softmax weight, normalize, ELU ========
// One warp per dst node, register accumulation, no atomics. Broadcast-style
// loads with x4 edge unroll: 4 independent g_s gathers + 4 z LDG.128 per iter.
__global__ void __launch_bounds__(256) k_agg(const float* __restrict__ abp,
                                             float* __restrict__ out) {
    int node = (blockIdx.x * blockDim.x + threadIdx.x) >> 5;
    if (node >= N_NODES) return;
    int lane = threadIdx.x & 31;
    float* __restrict__ op = out ? out : g_h1;

    int   off0 = g_off[node];
    int   off1 = g_off[node + 1];
    float td   = g_t[node] + abp[0];

    float4 acc = make_float4(0.f, 0.f, 0.f, 0.f);
    float  den = 0.f;
    const size_t zlane = (size_t)lane * 4;

    int j = off0;
    for (; j + 4 <= off1; j += 4) {
        int s0 = g_csr[j];
        int s1 = g_csr[j + 1];
        int s2 = g_csr[j + 2];
        int s3 = g_csr[j + 3];
        float e0 = g_s[s0] + td;
        float e1 = g_s[s1] + td;
        float e2 = g_s[s2] + td;
        float e3 = g_s[s3] + td;
        e0 = e0 > 0.f ? e0 : LEAKY * e0;
        e1 = e1 > 0.f ? e1 : LEAKY * e1;
        e2 = e2 > 0.f ? e2 : LEAKY * e2;
        e3 = e3 > 0.f ? e3 : LEAKY * e3;
        float x0 = __expf(e0);
        float x1 = __expf(e1);
        float x2 = __expf(e2);
        float x3 = __expf(e3);
        float4 z0 = *(const float4*)(&g_z[(size_t)s0 * HID + zlane]);
        float4 z1 = *(const float4*)(&g_z[(size_t)s1 * HID + zlane]);
        float4 z2 = *(const float4*)(&g_z[(size_t)s2 * HID + zlane]);
        float4 z3 = *(const float4*)(&g_z[(size_t)s3 * HID + zlane]);
        acc.x = fmaf(x0, z0.x, acc.x); acc.y = fmaf(x0, z0.y, acc.y);
        acc.z = fmaf(x0, z0.z, acc.z); acc.w = fmaf(x0, z0.w, acc.w);
        acc.x = fmaf(x1, z1.x, acc.x); acc.y = fmaf(x1, z1.y, acc.y);
        acc.z = fmaf(x1, z1.z, acc.z); acc.w = fmaf(x1, z1.w, acc.w);
        acc.x = fmaf(x2, z2.x, acc.x); acc.y = fmaf(x2, z2.y, acc.y);
        acc.z = fmaf(x2, z2.z, acc.z); acc.w = fmaf(x2, z2.w, acc.w);
        acc.x = fmaf(x3, z3.x, acc.x); acc.y = fmaf(x3, z3.y, acc.y);
        acc.z = fmaf(x3, z3.z, acc.z); acc.w = fmaf(x3, z3.w, acc.w);
        den += (x0 + x1) + (x2 + x3);
    }
    for (; j < off1; j++) {
        int s0 = g_csr[j];
        float e0 = g_s[s0] + td;
        e0 = e0 > 0.f ? e0 : LEAKY * e0;
        float x0 = __expf(e0);
        float4 z0 = *(const float4*)(&g_z[(size_t)s0 * HID + zlane]);
        acc.x = fmaf(x0, z0.x, acc.x); acc.y = fmaf(x0, z0.y, acc.y);
        acc.z = fmaf(x0, z0.z, acc.z); acc.w = fmaf(x0, z0.w, acc.w);
        den += x0;
    }

    float inv = den > 0.f ? 1.f / den : 0.f;
    float4 r;
    r.x = elu1(acc.x * inv);
    r.y = elu1(acc.y * inv);
    r.z = elu1(acc.z * inv);
    r.w = elu1(acc.w * inv);
    *(float4*)(&op[(size_t)node * HID + zlane]) = r;
}

// ---------------- launch ----------------
extern "C" void kernel_launch(void* const* d_in, const int* in_sizes, int n_in,
                              void* d_out, int out_size) {
    const float* h   = (const float*)d_in[0];
    const int*   src = (const int*)d_in[1];
    const int*   dst = (const int*)d_in[2];
    const float* W1  = (const float*)d_in[3];
    const float* b1  = (const float*)d_in[4];
    const float* a1  = (const float*)d_in[5];
    const float* ab1 = (const float*)d_in[6];
    const float* W2  = (const float*)d_in[7];
    const float* b2  = (const float*)d_in[8];
    const float* a2  = (const float*)d_in[9];
    const float* ab2 = (const float*)d_in[10];
    float* out = (float*)d_out;

    const int zeroB = (N_NODES + 255) / 256;
    const int edgeB = (N_EDGES + 255) / 256;
    const int gemmB = (N_NODES + 127) / 128;
    const int aggB  = (N_NODES * 32 + 255) / 256;

    // ---- CSR build (shared by both layers) ----
    k_zero<<<zeroB, 256>>>();
    k_hist<<<edgeB, 256>>>(dst);
    k_scan<<<1, 1024>>>();
    k_fill<<<edgeB, 256>>>(src, dst);

    // ---- layer 1 ----
    k_gemm_tc<IN_DIM><<<gemmB, 256>>>(h, W1, b1, a1);
    k_agg<<<aggB, 256>>>(ab1, nullptr);        // -> g_h1 (ELU applied)

    // ---- layer 2 ----
    k_gemm_tc<HID><<<gemmB, 256>>>(nullptr, W2, b2, a2);   // X = g_h1
    k_agg<<<aggB, 256>>>(ab2, out);
}